// round 17
// baseline (speedup 1.0000x reference)
#include <cuda_runtime.h>
#include <cstdint>

// SpectralConv2D fused kernel, R17 = R9 (best, 10.34us) + Phase-B split over
// 120 threads + 3-tap rolling y-batch in Phase C.
//   out[b,l,f] = relu( sum_tap base[f,tap] * (enc[n]-dec[l]) * up[b,n] )
// Block = (batch b, 2 output rows = 60 positions, 4 input rows = 128 px),
// 128 threads, grid (15, 64).

#define B_    64
#define W_    32
#define C_    8
#define F_    64
#define O2_   30
#define L_    900
#define N_    1024
#define TILE  60

__constant__ int c_sel[9] = {0,1,1,2,0,1,2,2,0};
__constant__ int c_t  [9] = {0,0,1,0,1,2,1,2,2};
__constant__ int c_i  [9] = {0,0,0,1,1,1,2,2,2};
__constant__ int c_j  [9] = {0,1,2,0,1,2,0,1,2};

__device__ __forceinline__ uint64_t ffma2(uint64_t a, uint64_t b, uint64_t c) {
    uint64_t d;
    asm("fma.rn.f32x2 %0, %1, %2, %3;" : "=l"(d) : "l"(a), "l"(b), "l"(c));
    return d;
}
__device__ __forceinline__ uint64_t fmul2(uint64_t a, uint64_t b) {
    uint64_t d;
    asm("mul.rn.f32x2 %0, %1, %2;" : "=l"(d) : "l"(a), "l"(b));
    return d;
}
__device__ __forceinline__ float2 u64_as_f2(uint64_t v) {
    union { uint64_t u; float2 f; } cv; cv.u = v; return cv.f;
}

__global__ __launch_bounds__(128)
void spectral_fused_kernel(
    const float* __restrict__ inputs,      // (B, 32, 32, 8)
    const float* __restrict__ omega_diag,  // (F, 3)
    const float* __restrict__ omega_triu,  // (F*3)
    const float* __restrict__ omega_tril,  // (F*3)
    const float* __restrict__ lambda_in,   // (3)
    const float* __restrict__ lambda_out,  // (3)
    const float* __restrict__ use_encode,  // (N)
    const float* __restrict__ use_decode,  // (L)
    float* __restrict__ out)               // (B, L, F)
{
    __shared__ __align__(16) float up_s[128];       // 4 input rows x 32
    __shared__ __align__(16) float eu_s[128];       // enc*up
    __shared__ __align__(16) float dec_s[64];
    __shared__ __align__(16) float base_s[9 * F_];  // [tap][f]
    __shared__ __align__(16) float y_d[9 * 128];    // [tap][pos dup x2], pos 0..63

    const int tid = threadIdx.x;
    const int kt  = blockIdx.x;            // 0..14
    const int b   = blockIdx.y;
    const int r0  = kt * 2;
    const int l0  = kt * TILE;

    // ---------------- Phase A: 1 pixel per thread ----------------
    {
        int n = r0 * W_ + tid;             // rows r0..r0+3
        const float4* p = (const float4*)(inputs + ((size_t)b * N_ + n) * C_);
        float4 v0 = p[0];
        float4 v1 = p[1];
        float m = (v0.x + v0.y + v0.z + v0.w + v1.x + v1.y + v1.z + v1.w) * 0.125f;
        up_s[tid] = m;
        eu_s[tid] = m * __ldg(&use_encode[n]);
    }
    if (tid < TILE)
        dec_s[tid] = __ldg(&use_decode[l0 + tid]);
    // zero-pad duplicated y for positions 60..63 (9 taps x 8 floats = 72)
    if (tid >= 56) {
        int k = tid - 56;                  // 0..71
        y_d[(k >> 3) * 128 + 120 + (k & 7)] = 0.f;
    }

    // branchless base assembly: 576 entries over 128 threads, layout [tap][f]
    {
        const float* srcs[3] = { omega_diag, omega_triu, omega_tril };
        #pragma unroll
        for (int k = 0; k < 5; k++) {
            int idx = tid + k * 128;
            if (k < 4 || tid < 64) {
                int pp = idx >> 6;
                int f  = idx & 63;
                float w = __ldg(&srcs[c_sel[pp]][f * 3 + c_t[pp]]);
                float lam = __ldg(&lambda_in[c_i[pp]]) - __ldg(&lambda_out[c_j[pp]]);
                base_s[idx] = w * lam;
            }
        }
    }
    __syncthreads();

    // ---------------- Phase B: split over 120 threads ----------------
    // threads 0..59: taps 0..4; threads 64..123: taps 5..8 (warp-aligned halves)
    {
        float2* yd = (float2*)y_d;                  // [tap*64 + pos]
        if (tid < TILE) {
            int pos = tid;
            float dec = dec_s[pos];
            int i0 = (pos >= 30) ? (pos + 2) : pos; // orow*32 + ocol
            #pragma unroll
            for (int tap = 0; tap < 5; tap++) {
                const int off = (tap / 3) * 32 + (tap % 3);
                float v = eu_s[i0 + off] - dec * up_s[i0 + off];
                yd[tap * 64 + pos] = make_float2(v, v);
            }
        } else if (tid >= 64 && tid < 64 + TILE) {
            int pos = tid - 64;
            float dec = dec_s[pos];
            int i0 = (pos >= 30) ? (pos + 2) : pos;
            #pragma unroll
            for (int tap = 5; tap < 9; tap++) {
                const int off = (tap / 3) * 32 + (tap % 3);
                float v = eu_s[i0 + off] - dec * up_s[i0 + off];
                yd[tap * 64 + pos] = make_float2(v, v);
            }
        }
    }
    __syncthreads();

    // ---------------- Phase C: 8 pos x 4 filters, 3-tap rolling batches ----------------
    const int f4 = tid & 15;               // filter quad
    const int g  = tid >> 4;               // 0..7 -> positions g*8..g*8+7

    uint64_t acc[8][2];
    #pragma unroll
    for (int t3 = 0; t3 < 9; t3 += 3) {
        // batch loads for 3 taps: 12 independent LDS.128 + 3 LDS.128 (w)
        ulonglong2 yb[3][4];
        ulonglong2 wb[3];
        #pragma unroll
        for (int k = 0; k < 3; k++) {
            const int tap = t3 + k;
            const ulonglong2* yrow = (const ulonglong2*)(y_d + tap * 128 + g * 16);
            yb[k][0] = yrow[0];
            yb[k][1] = yrow[1];
            yb[k][2] = yrow[2];
            yb[k][3] = yrow[3];
            wb[k] = *(const ulonglong2*)(base_s + tap * F_ + f4 * 4);
        }
        #pragma unroll
        for (int k = 0; k < 3; k++) {
            uint64_t wx = wb[k].x, wy = wb[k].y;
            #pragma unroll
            for (int q = 0; q < 4; q++) {
                uint64_t ye = yb[k][q].x;   // even pos dup
                uint64_t yo = yb[k][q].y;   // odd pos dup
                if (t3 == 0 && k == 0) {
                    acc[q * 2    ][0] = fmul2(ye, wx);
                    acc[q * 2    ][1] = fmul2(ye, wy);
                    acc[q * 2 + 1][0] = fmul2(yo, wx);
                    acc[q * 2 + 1][1] = fmul2(yo, wy);
                } else {
                    acc[q * 2    ][0] = ffma2(ye, wx, acc[q * 2    ][0]);
                    acc[q * 2    ][1] = ffma2(ye, wy, acc[q * 2    ][1]);
                    acc[q * 2 + 1][0] = ffma2(yo, wx, acc[q * 2 + 1][0]);
                    acc[q * 2 + 1][1] = ffma2(yo, wy, acc[q * 2 + 1][1]);
                }
            }
        }
    }

    float* obase = out + ((size_t)b * L_ + l0 + g * 8) * F_ + f4 * 4;
    #pragma unroll
    for (int p = 0; p < 8; p++) {
        int pos = g * 8 + p;
        if (pos < TILE) {
            float2 a0 = u64_as_f2(acc[p][0]);
            float2 a1 = u64_as_f2(acc[p][1]);
            float4 o;
            o.x = fmaxf(a0.x, 0.f);
            o.y = fmaxf(a0.y, 0.f);
            o.z = fmaxf(a1.x, 0.f);
            o.w = fmaxf(a1.y, 0.f);
            *(float4*)(obase + p * F_) = o;
        }
    }
}

extern "C" void kernel_launch(void* const* d_in, const int* in_sizes, int n_in,
                              void* d_out, int out_size) {
    (void)in_sizes; (void)n_in; (void)out_size;
    const float* inputs      = (const float*)d_in[0];
    const float* omega_diag  = (const float*)d_in[1];
    const float* omega_triu  = (const float*)d_in[2];
    const float* omega_tril  = (const float*)d_in[3];
    const float* lambda_in   = (const float*)d_in[4];
    const float* lambda_out  = (const float*)d_in[5];
    const float* use_encode  = (const float*)d_in[6];
    const float* use_decode  = (const float*)d_in[7];
    float* out = (float*)d_out;

    dim3 grid(L_ / TILE, B_);   // (15, 64) = 960 blocks
    spectral_fused_kernel<<<grid, 128>>>(
        inputs, omega_diag, omega_triu, omega_tril,
        lambda_in, lambda_out, use_encode, use_decode, out);
}